// round 7
// baseline (speedup 1.0000x reference)
#include <cuda_runtime.h>
#include <cuda_fp16.h>
#include <cstdint>

#define DD 1024
#define HH 4096
#define EE 8
#define TT 4096
#define BM 128
#define BNC 256
#define BK 64
#define RP 9216

// ---------------- scratch (device globals; no allocation) ----------------
__device__ __half g_Hh[(size_t)RP * HH];
__device__ __half g_Xh[(size_t)TT * DD];
__device__ __half g_W1h[(size_t)EE * HH * DD];
__device__ __half g_W2h[(size_t)EE * DD * HH];
__device__ float g_topw[TT * 2];
__device__ int   g_topi[TT * 2];
__device__ int   g_perm[RP];
__device__ float g_wrow[RP];
__device__ int   g_cnt[EE];
__device__ int   g_poff[EE + 1];
__device__ int   g_cur[EE];
// sync state
__device__ int g_ticket;
__device__ int g_zdone, g_rtdone, g_offdone, g_scdone;
__device__ int g_w1flag[128];
__device__ int g_w2flag[32];
__device__ int g_mdone[RP / BM];

// ticket layout
#define T_Z0   0
#define T_W1   64
#define T_RT   192
#define T_OFF  320
#define T_SC   321
#define T_W2   337
#define T_GEMM 369

// ---------------- helpers ----------------
__device__ __forceinline__ uint32_t smem_u32(const void* p) {
    uint32_t a;
    asm("{ .reg .u64 t; cvta.to.shared.u64 t, %1; cvt.u32.u64 %0, t; }" : "=r"(a) : "l"(p));
    return a;
}
__device__ __forceinline__ int ld_acq(const int* p) {
    int v;
    asm volatile("ld.acquire.gpu.global.b32 %0, [%1];" : "=r"(v) : "l"(p) : "memory");
    return v;
}
__device__ __forceinline__ void spin_eq(const int* p, int val) {
    while (ld_acq(p) != val) __nanosleep(128);
}
__device__ __forceinline__ void ldsm4(uint32_t& r0, uint32_t& r1, uint32_t& r2, uint32_t& r3,
                                      uint32_t addr) {
    asm volatile("ldmatrix.sync.aligned.m8n8.x4.shared.b16 {%0,%1,%2,%3}, [%4];"
                 : "=r"(r0), "=r"(r1), "=r"(r2), "=r"(r3) : "r"(addr));
}
__device__ __forceinline__ void mma_f16(float* d, uint32_t a0, uint32_t a1, uint32_t a2,
                                        uint32_t a3, uint32_t b0, uint32_t b1) {
    asm volatile("mma.sync.aligned.m16n8k16.row.col.f32.f16.f16.f32 "
                 "{%0,%1,%2,%3}, {%4,%5,%6,%7}, {%8,%9}, {%0,%1,%2,%3};"
                 : "+f"(d[0]), "+f"(d[1]), "+f"(d[2]), "+f"(d[3])
                 : "r"(a0), "r"(a1), "r"(a2), "r"(a3), "r"(b0), "r"(b1));
}
__device__ __forceinline__ float gelu_exact(float v) {
    return 0.5f * v * (1.0f + erff(v * 0.70710678118654752440f));
}
__device__ __forceinline__ void cp16(uint32_t dst, const void* src) {
    asm volatile("cp.async.cg.shared.global [%0], [%1], 16;" :: "r"(dst), "l"(src) : "memory");
}
#define CP_COMMIT() asm volatile("cp.async.commit_group;" ::: "memory")
#define CP_WAIT2()  asm volatile("cp.async.wait_group 2;" ::: "memory")
#define CP_WAIT0()  asm volatile("cp.async.wait_group 0;" ::: "memory")

__device__ __forceinline__ uint4 cvt8(float4 f0, float4 f1) {
    __half2 h0 = __floats2half2_rn(f0.x, f0.y), h1 = __floats2half2_rn(f0.z, f0.w);
    __half2 h2 = __floats2half2_rn(f1.x, f1.y), h3 = __floats2half2_rn(f1.z, f1.w);
    uint4 o;
    o.x = *(uint32_t*)&h0; o.y = *(uint32_t*)&h1;
    o.z = *(uint32_t*)&h2; o.w = *(uint32_t*)&h3;
    return o;
}

// ---------------- sync reset kernel ----------------
__global__ void init_sync() {
    int tid = threadIdx.x;
    if (tid == 0) {
        g_ticket = 0; g_zdone = 0; g_rtdone = 0; g_offdone = 0; g_scdone = 0;
    }
    if (tid < 128) g_w1flag[tid] = 0;
    if (tid < 32)  g_w2flag[tid] = 0;
    if (tid < RP / BM) g_mdone[tid] = 0;
    if (tid < EE) g_cnt[tid] = 0;
    for (int i = tid; i < RP; i += 256) g_wrow[i] = 0.f;
}

// ---------------- GEMM tile (round-5 proven mainloop) ----------------
#define A_ST (BM * BK * 2)
#define B_ST (BNC * BK * 2)
#define STG_B (A_ST + B_ST)
#define GEMM_SMEM (4 * STG_B)   // 192 KB

template <bool PHASE1>
__device__ void gemm_tile(char* smem, uint32_t smem_base, int m0, int n0, int e,
                          const __half* __restrict__ Bw, const float* __restrict__ bias,
                          float* __restrict__ out) {
    constexpr int N = PHASE1 ? HH : DD;
    constexpr int K = PHASE1 ? DD : HH;
    constexpr int NC = K / BK;

    const int tid  = threadIdx.x;
    const int warp = tid >> 5, lane = tid & 31;
    const int g = lane >> 2, t = lane & 3;
    const int wr = warp >> 2, wc = warp & 3;

    const int arow = tid >> 1, acb = (tid & 1) * 4;
    const __half* Abase = PHASE1 ? g_Xh : g_Hh;
    size_t arIdx = PHASE1 ? (size_t)__ldcg(&g_perm[m0 + arow]) : (size_t)(m0 + arow);
    const char* aSrc = (const char*)(Abase + arIdx * (size_t)K) + acb * 16;
    uint32_t aDst[4];
#pragma unroll
    for (int i = 0; i < 4; i++)
        aDst[i] = (uint32_t)arow * 128 + ((uint32_t)((acb + i) ^ (arow & 7)) << 4);
    const char* bSrc = (const char*)(Bw + ((size_t)e * N + n0 + tid) * (size_t)K);
    uint32_t bDst[8];
#pragma unroll
    for (int i = 0; i < 8; i++)
        bDst[i] = A_ST + (uint32_t)tid * 128 + ((uint32_t)(i ^ (tid & 7)) << 4);

    const int hiA = lane >> 4;
    const int hiB = (lane >> 3) & 1;
    uint32_t aOff[4], aXor[4];
#pragma unroll
    for (int mt = 0; mt < 4; mt++) {
        int r = wr * 64 + mt * 16 + (lane & 15);
        aOff[mt] = (uint32_t)r * 128;
        aXor[mt] = (uint32_t)(r & 7);
    }
    uint32_t bOff[4], bXor[4];
#pragma unroll
    for (int p = 0; p < 4; p++) {
        int r = wc * 64 + p * 16 + (lane & 7) + ((lane >> 4) << 3);
        bOff[p] = A_ST + (uint32_t)r * 128;
        bXor[p] = (uint32_t)(r & 7);
    }

    float acc[4][8][4];
#pragma unroll
    for (int i = 0; i < 4; i++)
#pragma unroll
        for (int j = 0; j < 8; j++)
#pragma unroll
            for (int r = 0; r < 4; r++) acc[i][j][r] = 0.f;

    auto issue = [&](int c) {
        uint32_t sb = smem_base + (c & 3) * STG_B;
        const char* as = aSrc + c * 128;
        const char* bs = bSrc + c * 128;
#pragma unroll
        for (int i = 0; i < 4; i++) cp16(sb + aDst[i], as + i * 16);
#pragma unroll
        for (int i = 0; i < 8; i++) cp16(sb + bDst[i], bs + i * 16);
    };

    issue(0); CP_COMMIT();
    issue(1); CP_COMMIT();
    issue(2); CP_COMMIT();

    for (int c = 0; c < NC; ++c) {
        CP_WAIT2();
        __syncthreads();
        if (c + 3 < NC) issue(c + 3);
        CP_COMMIT();

        const uint32_t stg = smem_base + (c & 3) * STG_B;
#pragma unroll
        for (int ks = 0; ks < 4; ks++) {
            uint32_t a[4][4];
#pragma unroll
            for (int mt = 0; mt < 4; mt++) {
                uint32_t ad = stg + aOff[mt] + (((uint32_t)(2 * ks + hiA) ^ aXor[mt]) << 4);
                ldsm4(a[mt][0], a[mt][1], a[mt][2], a[mt][3], ad);
            }
            uint32_t b[8][2];
#pragma unroll
            for (int p = 0; p < 4; p++) {
                uint32_t bd = stg + bOff[p] + (((uint32_t)(2 * ks + hiB) ^ bXor[p]) << 4);
                ldsm4(b[2 * p][0], b[2 * p][1], b[2 * p + 1][0], b[2 * p + 1][1], bd);
            }
#pragma unroll
            for (int mt = 0; mt < 4; mt++)
#pragma unroll
                for (int nt = 0; nt < 8; nt++)
                    mma_f16(acc[mt][nt], a[mt][0], a[mt][1], a[mt][2], a[mt][3],
                            b[nt][0], b[nt][1]);
        }
    }
    CP_WAIT0();

    const float* biasp = bias + (size_t)e * N;
    if (PHASE1) {
#pragma unroll
        for (int mt = 0; mt < 4; mt++) {
            int r0 = m0 + wr * 64 + mt * 16 + g;
#pragma unroll
            for (int nt = 0; nt < 8; nt++) {
                int nb = n0 + wc * 64 + nt * 8 + 2 * t;
                float b0v = biasp[nb], b1v = biasp[nb + 1];
                float v00 = gelu_exact(acc[mt][nt][0] + b0v);
                float v01 = gelu_exact(acc[mt][nt][1] + b1v);
                float v10 = gelu_exact(acc[mt][nt][2] + b0v);
                float v11 = gelu_exact(acc[mt][nt][3] + b1v);
                *(__half2*)&g_Hh[(size_t)r0 * HH + nb]       = __floats2half2_rn(v00, v01);
                *(__half2*)&g_Hh[(size_t)(r0 + 8) * HH + nb] = __floats2half2_rn(v10, v11);
            }
        }
    } else {
#pragma unroll
        for (int mt = 0; mt < 4; mt++) {
            int r0 = m0 + wr * 64 + mt * 16 + g;
            int tk0 = __ldcg(&g_perm[r0]);     float w0 = __ldcg(&g_wrow[r0]);
            int tk1 = __ldcg(&g_perm[r0 + 8]); float w1 = __ldcg(&g_wrow[r0 + 8]);
            float* o0 = out + (size_t)tk0 * DD;
            float* o1 = out + (size_t)tk1 * DD;
#pragma unroll
            for (int nt = 0; nt < 8; nt++) {
                int nb = n0 + wc * 64 + nt * 8 + 2 * t;
                float b0v = biasp[nb], b1v = biasp[nb + 1];
                atomicAdd(&o0[nb],     w0 * (acc[mt][nt][0] + b0v));
                atomicAdd(&o0[nb + 1], w0 * (acc[mt][nt][1] + b1v));
                atomicAdd(&o1[nb],     w1 * (acc[mt][nt][2] + b0v));
                atomicAdd(&o1[nb + 1], w1 * (acc[mt][nt][3] + b1v));
            }
        }
    }
    __syncthreads();
}

// ---------------- persistent fused kernel ----------------
__global__ __launch_bounds__(256, 1)
void moe_fused(const float* __restrict__ x,  const float* __restrict__ Wr,
               const float* __restrict__ br, const float* __restrict__ W1,
               const float* __restrict__ b1, const float* __restrict__ W2,
               const float* __restrict__ b2, float* __restrict__ out) {
    extern __shared__ char smem[];
    const uint32_t smem_base = smem_u32(smem);
    __shared__ int s_ticket;
    const int tid = threadIdx.x;

    for (;;) {
        __syncthreads();
        if (tid == 0) s_ticket = atomicAdd(&g_ticket, 1);
        __syncthreads();
        const int t = s_ticket;

        if (t < T_W1) {
            // zero output: 65536 floats per ticket
            float4 z = make_float4(0.f, 0.f, 0.f, 0.f);
            size_t base = (size_t)t * 65536;
#pragma unroll
            for (int i = 0; i < 64; i++)
                *(float4*)(out + base + (size_t)(i * 256 + tid) * 4) = z;
            __syncthreads();
            __threadfence();
            if (tid == 0) atomicAdd(&g_zdone, 1);
        } else if (t < T_RT) {
            // W1 convert block
            int b = t - T_W1;
            int e = b >> 4, n0 = (b & 15) * 256;
            const float4* src = (const float4*)(W1 + ((size_t)e * HH + n0) * DD);
            uint4* dst = (uint4*)(g_W1h + ((size_t)e * HH + n0) * DD);
#pragma unroll 4
            for (int i = 0; i < 128; i++) {
                int gi = i * 256 + tid;
                dst[gi] = cvt8(src[2 * gi], src[2 * gi + 1]);
            }
            __syncthreads();
            __threadfence();
            if (tid == 0) atomicExch(&g_w1flag[b], 1);
        } else if (t < T_OFF) {
            // router: 32 tokens
            int r = t - T_RT;
            float* sWr = (float*)smem;
            for (int i = tid; i < EE * DD / 4; i += 256)
                ((float4*)sWr)[i] = ((const float4*)Wr)[i];
            __syncthreads();
            int warp = tid >> 5, lane = tid & 31;
            for (int q = 0; q < 4; q++) {
                int tk = r * 32 + warp * 4 + q;
                const float4* xv = (const float4*)(x + (size_t)tk * DD);
                float acc[EE];
#pragma unroll
                for (int e = 0; e < EE; e++) acc[e] = 0.f;
#pragma unroll
                for (int i = 0; i < DD / 128; i++) {
                    float4 xs = xv[lane + i * 32];
#pragma unroll
                    for (int e = 0; e < EE; e++) {
                        float4 w = ((const float4*)(sWr + e * DD))[lane + i * 32];
                        acc[e] += xs.x * w.x + xs.y * w.y + xs.z * w.z + xs.w * w.w;
                    }
                }
#pragma unroll
                for (int rr = 0; rr < 4; rr++) {
                    int gi = lane + rr * 32;
                    ((uint4*)(g_Xh + (size_t)tk * DD))[gi] = cvt8(xv[2 * gi], xv[2 * gi + 1]);
                }
#pragma unroll
                for (int e = 0; e < EE; e++)
#pragma unroll
                    for (int off = 16; off > 0; off >>= 1)
                        acc[e] += __shfl_xor_sync(0xffffffffu, acc[e], off);
                if (lane == 0) {
                    float lg[EE];
                    float m = -1e30f;
#pragma unroll
                    for (int e = 0; e < EE; e++) { lg[e] = acc[e] + br[e]; m = fmaxf(m, lg[e]); }
                    float s = 0.f;
#pragma unroll
                    for (int e = 0; e < EE; e++) { lg[e] = expf(lg[e] - m); s += lg[e]; }
                    float inv = 1.f / s;
                    int i0 = 0; float v0 = lg[0];
#pragma unroll
                    for (int e = 1; e < EE; e++) if (lg[e] > v0) { v0 = lg[e]; i0 = e; }
                    int i1 = -1; float v1 = -1.f;
#pragma unroll
                    for (int e = 0; e < EE; e++) if (e != i0 && lg[e] > v1) { v1 = lg[e]; i1 = e; }
                    g_topi[2 * tk]     = i0;
                    g_topi[2 * tk + 1] = i1;
                    g_topw[2 * tk]     = v0 * inv;
                    g_topw[2 * tk + 1] = v1 * inv;
                    atomicAdd(&g_cnt[i0], 1);
                    atomicAdd(&g_cnt[i1], 1);
                }
            }
            __syncthreads();
            __threadfence();
            if (tid == 0) atomicAdd(&g_rtdone, 1);
        } else if (t == T_OFF) {
            if (tid == 0) {
                spin_eq(&g_rtdone, 128);
                int off = 0;
                for (int e = 0; e < EE; e++) {
                    g_poff[e] = off;
                    g_cur[e]  = off;
                    off += ((__ldcg(&g_cnt[e]) + BM - 1) / BM) * BM;
                }
                g_poff[EE] = off;
                __threadfence();
                atomicExch(&g_offdone, 1);
            }
        } else if (t < T_W2) {
            // scatter: 512 (token,slot) entries
            int s = t - T_SC;
            if (tid == 0) spin_eq(&g_offdone, 1);
            __syncthreads();
#pragma unroll
            for (int j = 0; j < 2; j++) {
                int idx = s * 512 + tid * 2 + j;
                int e = __ldcg(&g_topi[idx]);
                int pos = atomicAdd(&g_cur[e], 1);
                g_perm[pos] = idx >> 1;
                g_wrow[pos] = __ldcg(&g_topw[idx]);
            }
            __syncthreads();
            __threadfence();
            if (tid == 0) atomicAdd(&g_scdone, 1);
        } else if (t < T_GEMM) {
            // W2 convert block: 256 rows x 4096
            int b = t - T_W2;
            int e = b >> 2, n0 = (b & 3) * 256;
            const float4* src = (const float4*)(W2 + ((size_t)e * DD + n0) * HH);
            uint4* dst = (uint4*)(g_W2h + ((size_t)e * DD + n0) * HH);
#pragma unroll 4
            for (int i = 0; i < 512; i++) {
                int gi = i * 256 + tid;
                dst[gi] = cvt8(src[2 * gi], src[2 * gi + 1]);
            }
            __syncthreads();
            __threadfence();
            if (tid == 0) atomicExch(&g_w2flag[b], 1);
        } else {
            if (tid == 0) spin_eq(&g_offdone, 1);
            __syncthreads();
            const int tot = __ldcg(&g_poff[EE]);
            const int mta = tot >> 7;
            const int g1end = T_GEMM + 16 * mta;
            const int g2end = g1end + 4 * mta;
            if (t < g1end) {
                int k = t - T_GEMM;
                int mt = k >> 4, nt = k & 15;
                int m0 = mt * BM, n0 = nt * BNC;
                int e = 0;
#pragma unroll
                for (int i = 0; i < EE; i++) if (m0 >= __ldcg(&g_poff[i + 1])) e = i + 1;
                if (tid == 0) {
                    spin_eq(&g_scdone, 16);
                    spin_eq(&g_w1flag[e * 16 + nt], 1);
                }
                __syncthreads();
                gemm_tile<true>(smem, smem_base, m0, n0, e, g_W1h, b1, out);
                __threadfence();
                if (tid == 0) atomicAdd(&g_mdone[mt], 1);
            } else if (t < g2end) {
                int k = t - g1end;
                int mt = k >> 2, nt = k & 3;
                int m0 = mt * BM, n0 = nt * BNC;
                int e = 0;
#pragma unroll
                for (int i = 0; i < EE; i++) if (m0 >= __ldcg(&g_poff[i + 1])) e = i + 1;
                if (tid == 0) {
                    spin_eq(&g_mdone[mt], 16);
                    spin_eq(&g_w2flag[e * 4 + nt], 1);
                    spin_eq(&g_zdone, 64);
                }
                __syncthreads();
                gemm_tile<false>(smem, smem_base, m0, n0, e, g_W2h, b2, out);
            } else {
                break;
            }
        }
    }
}

// ---------------- launch ----------------
extern "C" void kernel_launch(void* const* d_in, const int* in_sizes, int n_in,
                              void* d_out, int out_size) {
    const float* x  = (const float*)d_in[0];
    const float* Wr = (const float*)d_in[1];
    const float* br = (const float*)d_in[2];
    const float* W1 = (const float*)d_in[3];
    const float* b1 = (const float*)d_in[4];
    const float* W2 = (const float*)d_in[5];
    const float* b2 = (const float*)d_in[6];
    float* out = (float*)d_out;
    (void)in_sizes; (void)n_in; (void)out_size;

    static int nsm = 0;
    if (!nsm) {
        cudaFuncSetAttribute(moe_fused, cudaFuncAttributeMaxDynamicSharedMemorySize, GEMM_SMEM);
        cudaDeviceGetAttribute(&nsm, cudaDevAttrMultiProcessorCount, 0);
        if (nsm <= 0) nsm = 148;
    }

    init_sync<<<1, 256>>>();
    moe_fused<<<nsm, 256, GEMM_SMEM>>>(x, Wr, br, W1, b1, W2, b2, out);
}